// round 3
// baseline (speedup 1.0000x reference)
#include <cuda_runtime.h>
#include <math.h>

#define BB   8
#define CC   64
#define CR   8
#define HH   64
#define WWD  64
#define NPIX 4096   // HH*WWD

// ---------------- device scratch (static, no allocation) ----------------
__device__ float d_avg[BB * CC];
__device__ float d_maxv[BB * CC];
__device__ float d_ca[BB * CC];
__device__ float d_sa_avg[BB * NPIX];
__device__ float d_sa_max[BB * NPIX];
// PAM fallback scratch (only written when gamma != 0)
__device__ float d_q[BB * CR * NPIX];
__device__ float d_k[BB * CR * NPIX];
__device__ float d_v[BB * CC * NPIX];
__device__ float d_pam[BB * CC * NPIX];

// ---------------- K1: per-(b,c) mean & max over HW ----------------
__global__ void k_chanstats(const float* __restrict__ x) {
    const int bc = blockIdx.x;                 // 0 .. B*C-1
    const float4* xp = reinterpret_cast<const float4*>(x + (size_t)bc * NPIX);
    float s = 0.0f, m = -INFINITY;
    #pragma unroll 4
    for (int i = threadIdx.x; i < NPIX / 4; i += 256) {
        float4 v = xp[i];
        s += (v.x + v.y) + (v.z + v.w);
        m = fmaxf(m, fmaxf(fmaxf(v.x, v.y), fmaxf(v.z, v.w)));
    }
    for (int off = 16; off > 0; off >>= 1) {
        s += __shfl_down_sync(0xffffffffu, s, off);
        m  = fmaxf(m, __shfl_down_sync(0xffffffffu, m, off));
    }
    __shared__ float ss[8], sm[8];
    const int wid = threadIdx.x >> 5, lid = threadIdx.x & 31;
    if (lid == 0) { ss[wid] = s; sm[wid] = m; }
    __syncthreads();
    if (threadIdx.x == 0) {
        float ts = 0.0f, tm = -INFINITY;
        #pragma unroll
        for (int i = 0; i < 8; i++) { ts += ss[i]; tm = fmaxf(tm, sm[i]); }
        d_avg[bc]  = ts * (1.0f / NPIX);
        d_maxv[bc] = tm;
    }
}

// ---------------- K2: spatial stats with fused channel-attention MLP ----------
// Each block recomputes the tiny MLP (1.5K MACs) from d_avg/d_maxv (L2-hit),
// then does the per-pixel mean/max over channels of x*ca.
__global__ void k_spatstats(const float* __restrict__ x,
                            const float* __restrict__ fc1,   // [CR, C]
                            const float* __restrict__ fc2) { // [C, CR]
    const int b = blockIdx.x >> 4;                         // 16 blocks / batch
    const int n = ((blockIdx.x & 15) << 8) + threadIdx.x;  // pixel
    const int t = threadIdx.x;
    __shared__ float ca[CC], h_avg[CR], h_mx[CR];
    // --- fused MLP ---
    if (t < CR) {
        float ha = 0.0f, hm = 0.0f;
        #pragma unroll
        for (int c = 0; c < CC; c++) {
            const float w = fc1[t * CC + c];
            ha += d_avg[b * CC + c] * w;
            hm += d_maxv[b * CC + c] * w;
        }
        h_avg[t] = fmaxf(ha, 0.0f);
        h_mx[t]  = fmaxf(hm, 0.0f);
    }
    __syncthreads();
    if (t < CC) {
        float o = 0.0f;
        #pragma unroll
        for (int r = 0; r < CR; r++)
            o += (h_avg[r] + h_mx[r]) * fc2[t * CR + r];
        const float s = 1.0f / (1.0f + expf(-o));
        ca[t] = s;
        d_ca[b * CC + t] = s;   // 16x redundant store, same value — benign
    }
    __syncthreads();
    // --- per-pixel channel stats ---
    const float* xb = x + (size_t)b * CC * NPIX;
    float s = 0.0f, m = -INFINITY;
    #pragma unroll
    for (int c = 0; c < CC; c++) {
        const float v = xb[c * NPIX + n] * ca[c];
        s += v;
        m = fmaxf(m, v);
    }
    d_sa_avg[b * NPIX + n] = s * (1.0f / CC);
    d_sa_max[b * NPIX + n] = m;
}

// ---------------- K3: FUSED 7x7 conv + sigmoid + final combine ----------------
// grid: 512 blocks = b(8) x pixel-chunk(16, 256 px each) x channel-group(4, 16 ch each)
// out = x * (1 + ca*sa_mask) + gamma*pam
__global__ void k_conv_final(const float* __restrict__ x,
                             const float* __restrict__ sw,     // [2,7,7]
                             const float* __restrict__ gamma,
                             float* __restrict__ out) {
    const int blk   = blockIdx.x;
    const int b     = blk >> 6;          // 0..7
    const int chunk = (blk >> 2) & 15;   // 0..15 -> pixels chunk*256
    const int cg    = blk & 3;           // channel group (16 channels)
    const int t     = threadIdx.x;       // 256 threads
    const int n0    = chunk << 8;        // first pixel
    const int h0    = chunk << 2;        // first row (4 rows per chunk)

    __shared__ float s_avg[10][70];      // rows h0-3 .. h0+6, cols -3..66
    __shared__ float s_max[10][70];
    __shared__ float wgt[98];
    __shared__ float mask[256];
    __shared__ float s_ca[16];

    if (t < 98) wgt[t] = sw[t];
    if (t < 16) s_ca[t] = d_ca[b * CC + cg * 16 + t];

    // load halo tile (zero-padded), 700 elements
    for (int i = t; i < 700; i += 256) {
        const int r = i / 70, cidx = i % 70;
        const int gh = h0 - 3 + r, gw = cidx - 3;
        float a = 0.0f, mval = 0.0f;
        if (gh >= 0 && gh < HH && gw >= 0 && gw < WWD) {
            const int gi = b * NPIX + gh * WWD + gw;
            a    = d_sa_avg[gi];
            mval = d_sa_max[gi];
        }
        s_avg[r][cidx] = a;
        s_max[r][cidx] = mval;
    }
    __syncthreads();

    // conv for this block's 256 pixels
    {
        const int h = t >> 6;   // 0..3 local row
        const int w = t & 63;   // col
        float acc = 0.0f;
        #pragma unroll
        for (int kh = 0; kh < 7; kh++) {
            #pragma unroll
            for (int kw = 0; kw < 7; kw++) {
                acc += s_avg[h + kh][w + kw] * wgt[kh * 7 + kw]
                     + s_max[h + kh][w + kw] * wgt[49 + kh * 7 + kw];
            }
        }
        mask[t] = 1.0f / (1.0f + expf(-acc));
    }
    __syncthreads();

    const float g = gamma[0];
    const float* xb = x + (size_t)(b * CC + cg * 16) * NPIX + n0;
    float* ob = out + (size_t)(b * CC + cg * 16) * NPIX + n0;
    const float msk = mask[t];
    if (g == 0.0f) {
        #pragma unroll
        for (int c = 0; c < 16; c++) {
            const float scale = 1.0f + s_ca[c] * msk;
            ob[c * NPIX + t] = xb[c * NPIX + t] * scale;
        }
    } else {
        const float* pb = d_pam + (size_t)(b * CC + cg * 16) * NPIX + n0;
        #pragma unroll
        for (int c = 0; c < 16; c++) {
            const float scale = 1.0f + s_ca[c] * msk;
            ob[c * NPIX + t] = xb[c * NPIX + t] * scale + g * pb[c * NPIX + t];
        }
    }
}

// ---------------- PAM fallback (executes only when gamma != 0) ----------------
// Tiny grids: the early-exit path (gamma==0, the benchmark case) costs ~node
// overhead only. The gamma!=0 path is grid-strided and fully correct.
__global__ void k_pam_qkv(const float* __restrict__ x,
                          const float* __restrict__ qw, const float* __restrict__ qb,
                          const float* __restrict__ kw, const float* __restrict__ kb,
                          const float* __restrict__ vw, const float* __restrict__ vb,
                          const float* __restrict__ gamma) {
    if (gamma[0] == 0.0f) return;
    __shared__ float sqw[CR * CC], skw[CR * CC], sqb[CR], skb[CR];
    for (int i = threadIdx.x; i < CR * CC; i += blockDim.x) { sqw[i] = qw[i]; skw[i] = kw[i]; }
    if (threadIdx.x < CR) { sqb[threadIdx.x] = qb[threadIdx.x]; skb[threadIdx.x] = kb[threadIdx.x]; }
    __syncthreads();
    for (int bn = blockIdx.x * blockDim.x + threadIdx.x; bn < BB * NPIX;
         bn += gridDim.x * blockDim.x) {
        const int b = bn >> 12, n = bn & (NPIX - 1);
        const float* xb = x + (size_t)b * CC * NPIX + n;
        float qa[CR], ka[CR];
        #pragma unroll
        for (int r = 0; r < CR; r++) { qa[r] = sqb[r]; ka[r] = skb[r]; }
        for (int c = 0; c < CC; c++) {
            const float xv = xb[c * NPIX];
            #pragma unroll
            for (int r = 0; r < CR; r++) {
                qa[r] += xv * sqw[r * CC + c];
                ka[r] += xv * skw[r * CC + c];
            }
        }
        #pragma unroll
        for (int r = 0; r < CR; r++) {
            d_q[(b * CR + r) * NPIX + n] = qa[r];
            d_k[(b * CR + r) * NPIX + n] = ka[r];
        }
    }
    for (int bcn = blockIdx.x * blockDim.x + threadIdx.x; bcn < BB * CC * NPIX;
         bcn += gridDim.x * blockDim.x) {
        const int bc = bcn >> 12;
        const int b = bc >> 6, c = bc & 63, n = bcn & (NPIX - 1);
        const float* xb = x + (size_t)b * CC * NPIX + n;
        float acc = vb[c];
        for (int cc = 0; cc < CC; cc++) acc += xb[cc * NPIX] * vw[c * CC + cc];
        d_v[bcn] = acc;
    }
}

__global__ void k_pam_attn(const float* __restrict__ gamma) {
    if (gamma[0] == 0.0f) return;
    __shared__ float att[NPIX];
    __shared__ float red[256];
    for (int row = blockIdx.x; row < BB * NPIX; row += gridDim.x) {
        const int b = row >> 12;
        const int i = row & (NPIX - 1);
        float qr[CR];
        #pragma unroll
        for (int r = 0; r < CR; r++) qr[r] = d_q[(b * CR + r) * NPIX + i];
        float mx = -INFINITY;
        for (int j = threadIdx.x; j < NPIX; j += 256) {
            float e = 0.0f;
            #pragma unroll
            for (int r = 0; r < CR; r++) e += qr[r] * d_k[(b * CR + r) * NPIX + j];
            att[j] = e;
            mx = fmaxf(mx, e);
        }
        red[threadIdx.x] = mx; __syncthreads();
        for (int s = 128; s > 0; s >>= 1) {
            if (threadIdx.x < s) red[threadIdx.x] = fmaxf(red[threadIdx.x], red[threadIdx.x + s]);
            __syncthreads();
        }
        mx = red[0]; __syncthreads();
        float sum = 0.0f;
        for (int j = threadIdx.x; j < NPIX; j += 256) {
            const float e = expf(att[j] - mx);
            att[j] = e;
            sum += e;
        }
        red[threadIdx.x] = sum; __syncthreads();
        for (int s = 128; s > 0; s >>= 1) {
            if (threadIdx.x < s) red[threadIdx.x] += red[threadIdx.x + s];
            __syncthreads();
        }
        const float inv = 1.0f / red[0]; __syncthreads();
        for (int c = 0; c < CC; c++) {
            float acc = 0.0f;
            for (int j = threadIdx.x; j < NPIX; j += 256)
                acc += att[j] * d_v[(b * CC + c) * NPIX + j];
            red[threadIdx.x] = acc; __syncthreads();
            for (int s = 128; s > 0; s >>= 1) {
                if (threadIdx.x < s) red[threadIdx.x] += red[threadIdx.x + s];
                __syncthreads();
            }
            if (threadIdx.x == 0) d_pam[(b * CC + c) * NPIX + i] = red[0] * inv;
            __syncthreads();
        }
    }
}

// ---------------- launch ----------------
extern "C" void kernel_launch(void* const* d_in, const int* in_sizes, int n_in,
                              void* d_out, int out_size) {
    const float* x     = (const float*)d_in[0];
    const float* fc1_w = (const float*)d_in[1];
    const float* fc2_w = (const float*)d_in[2];
    const float* q_w   = (const float*)d_in[3];
    const float* q_b   = (const float*)d_in[4];
    const float* k_w   = (const float*)d_in[5];
    const float* k_b   = (const float*)d_in[6];
    const float* v_w   = (const float*)d_in[7];
    const float* v_b   = (const float*)d_in[8];
    const float* gamma = (const float*)d_in[9];
    const float* sa_w  = (const float*)d_in[10];
    float* out = (float*)d_out;

    k_chanstats<<<BB * CC, 256>>>(x);
    k_spatstats<<<BB * 16, 256>>>(x, fc1_w, fc2_w);
    k_pam_qkv<<<64, 256>>>(x, q_w, q_b, k_w, k_b, v_w, v_b, gamma);
    k_pam_attn<<<64, 256>>>(gamma);
    k_conv_final<<<512, 256>>>(x, sa_w, gamma, out);
}

// round 5
// speedup vs baseline: 1.4034x; 1.4034x over previous
#include <cuda_runtime.h>
#include <math.h>

#define BB   8
#define CC   64
#define CR   8
#define HH   64
#define WWD  64
#define NPIX 4096   // HH*WWD
#define NBLK 128    // persistent grid: must be <= SM count (148)

// ---------------- device scratch (static, no allocation) ----------------
__device__ float d_avg[BB * CC];
__device__ float d_maxv[BB * CC];
__device__ float d_sa_avg[BB * NPIX];
__device__ float d_sa_max[BB * NPIX];
// PAM fallback scratch (only written when gamma != 0)
__device__ float d_q[BB * CR * NPIX];
__device__ float d_k[BB * CR * NPIX];
__device__ float d_v[BB * CC * NPIX];
__device__ __align__(16) float d_pam[BB * CC * NPIX];
// grid barrier ticket counter (monotonic; safe across graph replays)
__device__ unsigned long long g_bar;

// Software grid barrier. All NBLK blocks are co-resident (NBLK <= #SMs, 1 CTA
// worth of resources each), so spinning is deadlock-free. Monotonic ticket
// scheme: no reset needed between launches.
__device__ __forceinline__ void grid_barrier() {
    __syncthreads();
    if (threadIdx.x == 0) {
        __threadfence();
        const unsigned long long t = atomicAdd(&g_bar, 1ULL);
        const unsigned long long release = (t / NBLK + 1ULL) * (unsigned long long)NBLK;
        volatile unsigned long long* p = &g_bar;
        while (*p < release) { }
    }
    __syncthreads();
}

__global__ void __launch_bounds__(256, 1)
k_pcbam(const float* __restrict__ x,
        const float* __restrict__ fc1,   // [CR, C]
        const float* __restrict__ fc2,   // [C, CR]
        const float* __restrict__ qw, const float* __restrict__ qbias,
        const float* __restrict__ kw, const float* __restrict__ kbias,
        const float* __restrict__ vw, const float* __restrict__ vbias,
        const float* __restrict__ gamma,
        const float* __restrict__ sw,    // [2,7,7]
        float* __restrict__ out) {
    const int blk = blockIdx.x;   // 0..127
    const int t   = threadIdx.x;  // 0..255

    __shared__ float red_s[8], red_m[8];
    __shared__ float ca[CC], h_avg[CR], h_mx[CR];
    __shared__ float s_avg[10][70], s_max[10][70];
    __shared__ float wgt[98];
    __shared__ __align__(16) float mask[256];
    __shared__ float att[NPIX];   // PAM fallback only
    __shared__ float red[256];    // PAM fallback only

    const float g = gamma[0];

    // ================= Phase A: per-(b,c) mean & max over HW =================
    // 512 rows / 128 blocks = 4 rows per block, 4096 floats each.
    #pragma unroll
    for (int i = 0; i < 4; i++) {
        const int bc = blk * 4 + i;
        const float4* xp = reinterpret_cast<const float4*>(x + (size_t)bc * NPIX);
        float s = 0.0f, m = -INFINITY;
        #pragma unroll
        for (int j = 0; j < 4; j++) {
            const float4 v = xp[t + j * 256];
            s += (v.x + v.y) + (v.z + v.w);
            m = fmaxf(m, fmaxf(fmaxf(v.x, v.y), fmaxf(v.z, v.w)));
        }
        #pragma unroll
        for (int off = 16; off; off >>= 1) {
            s += __shfl_down_sync(0xffffffffu, s, off);
            m  = fmaxf(m, __shfl_down_sync(0xffffffffu, m, off));
        }
        if ((t & 31) == 0) { red_s[t >> 5] = s; red_m[t >> 5] = m; }
        __syncthreads();
        if (t == 0) {
            float ts = 0.0f, tm = -INFINITY;
            #pragma unroll
            for (int w = 0; w < 8; w++) { ts += red_s[w]; tm = fmaxf(tm, red_m[w]); }
            d_avg[bc]  = ts * (1.0f / NPIX);
            d_maxv[bc] = tm;
        }
        __syncthreads();
    }

    grid_barrier();

    // ================= Phase B: fused MLP + spatial stats =================
    const int b     = blk >> 4;          // batch
    const int chunk = blk & 15;          // 256-pixel chunk
    const int n0    = chunk << 8;

    if (t < CR) {
        float ha = 0.0f, hm = 0.0f;
        #pragma unroll
        for (int c = 0; c < CC; c++) {
            const float w = fc1[t * CC + c];
            ha += __ldcg(&d_avg[b * CC + c])  * w;
            hm += __ldcg(&d_maxv[b * CC + c]) * w;
        }
        h_avg[t] = fmaxf(ha, 0.0f);
        h_mx[t]  = fmaxf(hm, 0.0f);
    }
    __syncthreads();
    if (t < CC) {
        float o = 0.0f;
        #pragma unroll
        for (int r = 0; r < CR; r++)
            o += (h_avg[r] + h_mx[r]) * fc2[t * CR + r];
        ca[t] = 1.0f / (1.0f + expf(-o));
    }
    __syncthreads();
    {
        const int n = n0 + t;
        const float* xb = x + (size_t)b * CC * NPIX;
        float s = 0.0f, m = -INFINITY;
        #pragma unroll
        for (int c = 0; c < CC; c++) {
            const float v = xb[c * NPIX + n] * ca[c];
            s += v;
            m = fmaxf(m, v);
        }
        d_sa_avg[b * NPIX + n] = s * (1.0f / CC);
        d_sa_max[b * NPIX + n] = m;
    }

    // ================= PAM fallback (uniform branch; benchmark: g==0) ========
    if (g != 0.0f) {
        grid_barrier();
        // q,k projections
        for (int bn = blk * 256 + t; bn < BB * NPIX; bn += NBLK * 256) {
            const int bb = bn >> 12, n = bn & (NPIX - 1);
            const float* xb = x + (size_t)bb * CC * NPIX + n;
            float qa[CR], ka[CR];
            #pragma unroll
            for (int r = 0; r < CR; r++) { qa[r] = qbias[r]; ka[r] = kbias[r]; }
            for (int c = 0; c < CC; c++) {
                const float xv = xb[c * NPIX];
                #pragma unroll
                for (int r = 0; r < CR; r++) {
                    qa[r] += xv * qw[r * CC + c];
                    ka[r] += xv * kw[r * CC + c];
                }
            }
            #pragma unroll
            for (int r = 0; r < CR; r++) {
                d_q[(bb * CR + r) * NPIX + n] = qa[r];
                d_k[(bb * CR + r) * NPIX + n] = ka[r];
            }
        }
        // v projection
        for (int bcn = blk * 256 + t; bcn < BB * CC * NPIX; bcn += NBLK * 256) {
            const int bc = bcn >> 12;
            const int bb = bc >> 6, c = bc & 63, n = bcn & (NPIX - 1);
            const float* xb = x + (size_t)bb * CC * NPIX + n;
            float acc = vbias[c];
            for (int cc = 0; cc < CC; cc++) acc += xb[cc * NPIX] * vw[c * CC + cc];
            d_v[bcn] = acc;
        }
        grid_barrier();
        // attention rows
        for (int row = blk; row < BB * NPIX; row += NBLK) {
            const int bb = row >> 12;
            const int i  = row & (NPIX - 1);
            float qr[CR];
            #pragma unroll
            for (int r = 0; r < CR; r++) qr[r] = __ldcg(&d_q[(bb * CR + r) * NPIX + i]);
            float mx = -INFINITY;
            for (int j = t; j < NPIX; j += 256) {
                float e = 0.0f;
                #pragma unroll
                for (int r = 0; r < CR; r++) e += qr[r] * __ldcg(&d_k[(bb * CR + r) * NPIX + j]);
                att[j] = e;
                mx = fmaxf(mx, e);
            }
            red[t] = mx; __syncthreads();
            for (int s = 128; s; s >>= 1) {
                if (t < s) red[t] = fmaxf(red[t], red[t + s]);
                __syncthreads();
            }
            mx = red[0]; __syncthreads();
            float sum = 0.0f;
            for (int j = t; j < NPIX; j += 256) {
                const float e = expf(att[j] - mx);
                att[j] = e;
                sum += e;
            }
            red[t] = sum; __syncthreads();
            for (int s = 128; s; s >>= 1) {
                if (t < s) red[t] += red[t + s];
                __syncthreads();
            }
            const float inv = 1.0f / red[0]; __syncthreads();
            for (int c = 0; c < CC; c++) {
                float acc = 0.0f;
                for (int j = t; j < NPIX; j += 256)
                    acc += att[j] * __ldcg(&d_v[(bb * CC + c) * NPIX + j]);
                red[t] = acc; __syncthreads();
                for (int s = 128; s; s >>= 1) {
                    if (t < s) red[t] += red[t + s];
                    __syncthreads();
                }
                if (t == 0) d_pam[(bb * CC + c) * NPIX + i] = red[0] * inv;
                __syncthreads();
            }
        }
    }

    grid_barrier();

    // ================= Phase C: 7x7 conv + sigmoid + final combine ==========
    if (t < 98) wgt[t] = sw[t];
    const int h0 = chunk << 2;
    for (int i = t; i < 700; i += 256) {
        const int r = i / 70, cidx = i % 70;
        const int gh = h0 - 3 + r, gw = cidx - 3;
        float a = 0.0f, mv = 0.0f;
        if (gh >= 0 && gh < HH && (unsigned)gw < (unsigned)WWD) {
            const int gi = b * NPIX + gh * WWD + gw;
            a  = __ldcg(&d_sa_avg[gi]);
            mv = __ldcg(&d_sa_max[gi]);
        }
        s_avg[r][cidx] = a;
        s_max[r][cidx] = mv;
    }
    __syncthreads();
    {
        const int h = t >> 6, w = t & 63;
        float acc = 0.0f;
        #pragma unroll
        for (int kh = 0; kh < 7; kh++)
            #pragma unroll
            for (int kw2 = 0; kw2 < 7; kw2++)
                acc += s_avg[h + kh][w + kw2] * wgt[kh * 7 + kw2]
                     + s_max[h + kh][w + kw2] * wgt[49 + kh * 7 + kw2];
        mask[t] = 1.0f / (1.0f + expf(-acc));
    }
    __syncthreads();
    {
        const int lane4 = t & 63;   // float4 index within the 256-px chunk
        const int c0    = t >> 6;   // 0..3
        const float4 m4 = reinterpret_cast<const float4*>(mask)[lane4];
        const size_t base4 = (size_t)b * CC * (NPIX / 4) + (size_t)(n0 / 4) + lane4;
        if (g == 0.0f) {
            #pragma unroll
            for (int k = 0; k < 16; k++) {
                const int c = c0 + 4 * k;
                const size_t idx4 = base4 + (size_t)c * (NPIX / 4);
                const float4 xv = reinterpret_cast<const float4*>(x)[idx4];
                const float cav = ca[c];
                float4 o;
                o.x = xv.x * (1.0f + cav * m4.x);
                o.y = xv.y * (1.0f + cav * m4.y);
                o.z = xv.z * (1.0f + cav * m4.z);
                o.w = xv.w * (1.0f + cav * m4.w);
                reinterpret_cast<float4*>(out)[idx4] = o;
            }
        } else {
            #pragma unroll
            for (int k = 0; k < 16; k++) {
                const int c = c0 + 4 * k;
                const size_t idx4 = base4 + (size_t)c * (NPIX / 4);
                const float4 xv = reinterpret_cast<const float4*>(x)[idx4];
                const float4 pv = reinterpret_cast<const float4*>(d_pam)[idx4];
                const float cav = ca[c];
                float4 o;
                o.x = xv.x * (1.0f + cav * m4.x) + g * pv.x;
                o.y = xv.y * (1.0f + cav * m4.y) + g * pv.y;
                o.z = xv.z * (1.0f + cav * m4.z) + g * pv.z;
                o.w = xv.w * (1.0f + cav * m4.w) + g * pv.w;
                reinterpret_cast<float4*>(out)[idx4] = o;
            }
        }
    }
}

// ---------------- launch ----------------
extern "C" void kernel_launch(void* const* d_in, const int* in_sizes, int n_in,
                              void* d_out, int out_size) {
    const float* x     = (const float*)d_in[0];
    const float* fc1_w = (const float*)d_in[1];
    const float* fc2_w = (const float*)d_in[2];
    const float* q_w   = (const float*)d_in[3];
    const float* q_b   = (const float*)d_in[4];
    const float* k_w   = (const float*)d_in[5];
    const float* k_b   = (const float*)d_in[6];
    const float* v_w   = (const float*)d_in[7];
    const float* v_b   = (const float*)d_in[8];
    const float* gamma = (const float*)d_in[9];
    const float* sa_w  = (const float*)d_in[10];
    float* out = (float*)d_out;

    k_pcbam<<<NBLK, 256>>>(x, fc1_w, fc2_w, q_w, q_b, k_w, k_b, v_w, v_b,
                           gamma, sa_w, out);
}

// round 6
// speedup vs baseline: 1.5161x; 1.0803x over previous
#include <cuda_runtime.h>
#include <math.h>

#define BB   8
#define CC   64
#define CR   8
#define HH   64
#define WWD  64
#define NPIX 4096   // HH*WWD
#define NBLK 128    // persistent grid: must be <= SM count (148)
#define NTHR 1024

// ---------------- device scratch (static, no allocation) ----------------
__device__ float d_avg[BB * CC];
__device__ float d_maxv[BB * CC];
__device__ float d_sa_avg[BB * NPIX];
__device__ float d_sa_max[BB * NPIX];
// PAM fallback scratch (only written when gamma != 0)
__device__ float d_q[BB * CR * NPIX];
__device__ float d_k[BB * CR * NPIX];
__device__ float d_v[BB * CC * NPIX];
__device__ __align__(16) float d_pam[BB * CC * NPIX];
// grid barrier ticket counter (monotonic; safe across graph replays)
__device__ unsigned long long g_bar;

// Software grid barrier. All NBLK blocks are co-resident (NBLK <= #SMs, 1 CTA
// each), so spinning is deadlock-free. Monotonic ticket scheme: no reset needed.
__device__ __forceinline__ void grid_barrier() {
    __syncthreads();
    if (threadIdx.x == 0) {
        __threadfence();
        const unsigned long long t = atomicAdd(&g_bar, 1ULL);
        const unsigned long long release = (t / NBLK + 1ULL) * (unsigned long long)NBLK;
        volatile unsigned long long* p = &g_bar;
        while (*p < release) { }
    }
    __syncthreads();
}

__global__ void __launch_bounds__(NTHR, 1)
k_pcbam(const float* __restrict__ x,
        const float* __restrict__ fc1,   // [CR, C]
        const float* __restrict__ fc2,   // [C, CR]
        const float* __restrict__ qw, const float* __restrict__ qbias,
        const float* __restrict__ kw, const float* __restrict__ kbias,
        const float* __restrict__ vw, const float* __restrict__ vbias,
        const float* __restrict__ gamma,
        const float* __restrict__ sw,    // [2,7,7]
        float* __restrict__ out) {
    const int blk = blockIdx.x;   // 0..127
    const int t   = threadIdx.x;  // 0..1023

    __shared__ float red_s[32], red_m[32];          // per-warp partials (phase A)
    __shared__ float ca[CC], h_avg[CR], h_mx[CR];
    __shared__ float ps[4][256], pm[4][256];        // phase B partials
    __shared__ float s_avg[10][70], s_max[10][70];
    __shared__ float wgt[98];
    __shared__ __align__(16) float mask[256];
    __shared__ float att[NPIX];    // PAM fallback only
    __shared__ float red[NTHR];    // PAM fallback only

    const float g = gamma[0];
    const int wid = t >> 5, lid = t & 31;

    // ================= Phase A: per-(b,c) mean & max over HW =================
    // 512 rows / 128 blocks = 4 rows/block; one row per 256-thread group.
    {
        const int row  = t >> 8;        // 0..3
        const int rtid = t & 255;       // thread within row-group
        const int bc   = blk * 4 + row;
        const float4* xp = reinterpret_cast<const float4*>(x + (size_t)bc * NPIX);
        float s = 0.0f, m = -INFINITY;
        #pragma unroll
        for (int j = 0; j < 4; j++) {
            const float4 v = xp[rtid + j * 256];
            s += (v.x + v.y) + (v.z + v.w);
            m = fmaxf(m, fmaxf(fmaxf(v.x, v.y), fmaxf(v.z, v.w)));
        }
        #pragma unroll
        for (int off = 16; off; off >>= 1) {
            s += __shfl_down_sync(0xffffffffu, s, off);
            m  = fmaxf(m, __shfl_down_sync(0xffffffffu, m, off));
        }
        if (lid == 0) { red_s[wid] = s; red_m[wid] = m; }
        __syncthreads();
        if (rtid == 0) {          // one thread per row-group (wid = row*8)
            float ts = 0.0f, tm = -INFINITY;
            #pragma unroll
            for (int w = 0; w < 8; w++) {
                ts += red_s[row * 8 + w];
                tm = fmaxf(tm, red_m[row * 8 + w]);
            }
            d_avg[bc]  = ts * (1.0f / NPIX);
            d_maxv[bc] = tm;
        }
    }

    grid_barrier();

    // ================= Phase B: fused MLP + spatial stats =================
    const int b     = blk >> 4;          // batch
    const int chunk = blk & 15;          // 256-pixel chunk
    const int n0    = chunk << 8;

    if (t < CR) {
        float ha = 0.0f, hm = 0.0f;
        #pragma unroll
        for (int c = 0; c < CC; c++) {
            const float w = fc1[t * CC + c];
            ha += __ldcg(&d_avg[b * CC + c])  * w;
            hm += __ldcg(&d_maxv[b * CC + c]) * w;
        }
        h_avg[t] = fmaxf(ha, 0.0f);
        h_mx[t]  = fmaxf(hm, 0.0f);
    }
    __syncthreads();
    if (t < CC) {
        float o = 0.0f;
        #pragma unroll
        for (int r = 0; r < CR; r++)
            o += (h_avg[r] + h_mx[r]) * fc2[t * CR + r];
        ca[t] = 1.0f / (1.0f + expf(-o));
    }
    __syncthreads();
    {
        const int px  = t & 255;        // pixel within chunk
        const int grp = t >> 8;         // channel group 0..3 (16 ch each)
        const int n   = n0 + px;
        const float* xb = x + (size_t)b * CC * NPIX + n;
        float s = 0.0f, m = -INFINITY;
        #pragma unroll
        for (int cc = 0; cc < 16; cc++) {
            const int c = grp * 16 + cc;
            const float v = xb[c * NPIX] * ca[c];
            s += v;
            m = fmaxf(m, v);
        }
        ps[grp][px] = s;
        pm[grp][px] = m;
        __syncthreads();
        if (t < 256) {
            float ts = ps[0][t] + ps[1][t] + ps[2][t] + ps[3][t];
            float tm = fmaxf(fmaxf(pm[0][t], pm[1][t]), fmaxf(pm[2][t], pm[3][t]));
            d_sa_avg[b * NPIX + n0 + t] = ts * (1.0f / CC);
            d_sa_max[b * NPIX + n0 + t] = tm;
        }
    }

    // ================= PAM fallback (uniform branch; benchmark: g==0) ========
    if (g != 0.0f) {
        grid_barrier();
        for (int bn = blk * NTHR + t; bn < BB * NPIX; bn += NBLK * NTHR) {
            const int bb = bn >> 12, n = bn & (NPIX - 1);
            const float* xb = x + (size_t)bb * CC * NPIX + n;
            float qa[CR], ka[CR];
            #pragma unroll
            for (int r = 0; r < CR; r++) { qa[r] = qbias[r]; ka[r] = kbias[r]; }
            for (int c = 0; c < CC; c++) {
                const float xv = xb[c * NPIX];
                #pragma unroll
                for (int r = 0; r < CR; r++) {
                    qa[r] += xv * qw[r * CC + c];
                    ka[r] += xv * kw[r * CC + c];
                }
            }
            #pragma unroll
            for (int r = 0; r < CR; r++) {
                d_q[(bb * CR + r) * NPIX + n] = qa[r];
                d_k[(bb * CR + r) * NPIX + n] = ka[r];
            }
        }
        for (int bcn = blk * NTHR + t; bcn < BB * CC * NPIX; bcn += NBLK * NTHR) {
            const int bc = bcn >> 12;
            const int bb = bc >> 6, c = bc & 63, n = bcn & (NPIX - 1);
            const float* xb = x + (size_t)bb * CC * NPIX + n;
            float acc = vbias[c];
            for (int cc = 0; cc < CC; cc++) acc += xb[cc * NPIX] * vw[c * CC + cc];
            d_v[bcn] = acc;
        }
        grid_barrier();
        for (int row = blk; row < BB * NPIX; row += NBLK) {
            const int bb = row >> 12;
            const int i  = row & (NPIX - 1);
            float qr[CR];
            #pragma unroll
            for (int r = 0; r < CR; r++) qr[r] = __ldcg(&d_q[(bb * CR + r) * NPIX + i]);
            float mx = -INFINITY;
            for (int j = t; j < NPIX; j += NTHR) {
                float e = 0.0f;
                #pragma unroll
                for (int r = 0; r < CR; r++) e += qr[r] * __ldcg(&d_k[(bb * CR + r) * NPIX + j]);
                att[j] = e;
                mx = fmaxf(mx, e);
            }
            red[t] = mx; __syncthreads();
            for (int s = NTHR / 2; s; s >>= 1) {
                if (t < s) red[t] = fmaxf(red[t], red[t + s]);
                __syncthreads();
            }
            mx = red[0]; __syncthreads();
            float sum = 0.0f;
            for (int j = t; j < NPIX; j += NTHR) {
                const float e = expf(att[j] - mx);
                att[j] = e;
                sum += e;
            }
            red[t] = sum; __syncthreads();
            for (int s = NTHR / 2; s; s >>= 1) {
                if (t < s) red[t] += red[t + s];
                __syncthreads();
            }
            const float inv = 1.0f / red[0]; __syncthreads();
            for (int c = 0; c < CC; c++) {
                float acc = 0.0f;
                for (int j = t; j < NPIX; j += NTHR)
                    acc += att[j] * __ldcg(&d_v[(bb * CC + c) * NPIX + j]);
                red[t] = acc; __syncthreads();
                for (int s = NTHR / 2; s; s >>= 1) {
                    if (t < s) red[t] += red[t + s];
                    __syncthreads();
                }
                if (t == 0) d_pam[(bb * CC + c) * NPIX + i] = red[0] * inv;
                __syncthreads();
            }
        }
    }

    grid_barrier();

    // ================= Phase C: 7x7 conv + sigmoid + final combine ==========
    if (t < 98) wgt[t] = sw[t];
    const int h0 = chunk << 2;
    for (int i = t; i < 700; i += NTHR) {
        const int r = i / 70, cidx = i % 70;
        const int gh = h0 - 3 + r, gw = cidx - 3;
        float a = 0.0f, mv = 0.0f;
        if (gh >= 0 && gh < HH && (unsigned)gw < (unsigned)WWD) {
            const int gi = b * NPIX + gh * WWD + gw;
            a  = __ldcg(&d_sa_avg[gi]);
            mv = __ldcg(&d_sa_max[gi]);
        }
        s_avg[r][cidx] = a;
        s_max[r][cidx] = mv;
    }
    __syncthreads();
    if (t < 256) {
        const int h = t >> 6, w = t & 63;
        float acc = 0.0f;
        #pragma unroll
        for (int kh = 0; kh < 7; kh++)
            #pragma unroll
            for (int kw2 = 0; kw2 < 7; kw2++)
                acc += s_avg[h + kh][w + kw2] * wgt[kh * 7 + kw2]
                     + s_max[h + kh][w + kw2] * wgt[49 + kh * 7 + kw2];
        mask[t] = 1.0f / (1.0f + expf(-acc));
    }
    __syncthreads();
    {
        const int lane4 = t & 63;   // float4 index within the 256-px chunk
        const int c0    = t >> 6;   // 0..15
        const float4 m4 = reinterpret_cast<const float4*>(mask)[lane4];
        const size_t base4 = (size_t)b * CC * (NPIX / 4) + (size_t)(n0 / 4) + lane4;
        if (g == 0.0f) {
            #pragma unroll
            for (int k = 0; k < 4; k++) {
                const int c = c0 + 16 * k;
                const size_t idx4 = base4 + (size_t)c * (NPIX / 4);
                const float4 xv = reinterpret_cast<const float4*>(x)[idx4];
                const float cav = ca[c];
                float4 o;
                o.x = xv.x * (1.0f + cav * m4.x);
                o.y = xv.y * (1.0f + cav * m4.y);
                o.z = xv.z * (1.0f + cav * m4.z);
                o.w = xv.w * (1.0f + cav * m4.w);
                reinterpret_cast<float4*>(out)[idx4] = o;
            }
        } else {
            #pragma unroll
            for (int k = 0; k < 4; k++) {
                const int c = c0 + 16 * k;
                const size_t idx4 = base4 + (size_t)c * (NPIX / 4);
                const float4 xv = reinterpret_cast<const float4*>(x)[idx4];
                const float4 pv = reinterpret_cast<const float4*>(d_pam)[idx4];
                const float cav = ca[c];
                float4 o;
                o.x = xv.x * (1.0f + cav * m4.x) + g * pv.x;
                o.y = xv.y * (1.0f + cav * m4.y) + g * pv.y;
                o.z = xv.z * (1.0f + cav * m4.z) + g * pv.z;
                o.w = xv.w * (1.0f + cav * m4.w) + g * pv.w;
                reinterpret_cast<float4*>(out)[idx4] = o;
            }
        }
    }
}

// ---------------- launch ----------------
extern "C" void kernel_launch(void* const* d_in, const int* in_sizes, int n_in,
                              void* d_out, int out_size) {
    const float* x     = (const float*)d_in[0];
    const float* fc1_w = (const float*)d_in[1];
    const float* fc2_w = (const float*)d_in[2];
    const float* q_w   = (const float*)d_in[3];
    const float* q_b   = (const float*)d_in[4];
    const float* k_w   = (const float*)d_in[5];
    const float* k_b   = (const float*)d_in[6];
    const float* v_w   = (const float*)d_in[7];
    const float* v_b   = (const float*)d_in[8];
    const float* gamma = (const float*)d_in[9];
    const float* sa_w  = (const float*)d_in[10];
    float* out = (float*)d_out;

    k_pcbam<<<NBLK, NTHR>>>(x, fc1_w, fc2_w, q_w, q_b, k_w, k_b, v_w, v_b,
                            gamma, sa_w, out);
}